// round 3
// baseline (speedup 1.0000x reference)
#include <cuda_runtime.h>
#include <cstdint>

#define NN      8192
#define THREADS 512
#define NCTA    148
#define WARPS_PER_CTA (THREADS / 32)
#define NWARPS  (NCTA * WARPS_PER_CTA)      // 2368
#define COLB    128                          // columns per unit
#define ROWB    32                           // rows per unit (= warp size)
#define NCOLB   (NN / COLB)                  // 64
#define NROWB   (NN / ROWB)                  // 256
#define NUNITS  (NCOLB * NROWB)              // 16384

// scratch (allocation-free rule: __device__ globals; zero-initialized at load,
// re-zeroed by the last CTA each launch so graph replays are deterministic)
__device__ float g_dot[NN * 3];
__device__ int   g_deg[NN];
__device__ int   g_done;

__device__ __forceinline__ uint64_t ffma2(uint64_t a, uint64_t b, uint64_t c) {
    uint64_t d;
    asm("fma.rn.f32x2 %0, %1, %2, %3;" : "=l"(d) : "l"(a), "l"(b), "l"(c));
    return d;
}
__device__ __forceinline__ uint64_t pack2(float lo, float hi) {
    uint64_t d;
    asm("mov.b64 %0, {%1, %2};" : "=l"(d) : "f"(lo), "f"(hi));
    return d;
}
__device__ __forceinline__ float hadd2(uint64_t a) {
    float lo, hi;
    asm("mov.b64 {%0,%1}, %2;" : "=f"(lo), "=f"(hi) : "l"(a));
    return lo + hi;
}

__global__ void __launch_bounds__(THREADS, 1)
lap_kernel(const float* __restrict__ pred1,
           const float* __restrict__ pred2,
           const float* __restrict__ A,
           float* __restrict__ out) {
    extern __shared__ float smem[];
    float* sp0 = smem;            // p, SoA
    float* sp1 = smem + NN;
    float* sp2 = smem + 2 * NN;
    float* red = smem + 3 * NN;   // 16 floats warp-reduce scratch

    const int tid  = threadIdx.x;
    const int lane = tid & 31;
    const int warp = tid >> 5;

    // ---- stage p = pred2 - pred1 into smem (SoA), fused prep ----
    {
        const float4* q1 = reinterpret_cast<const float4*>(pred1);
        const float4* q2 = reinterpret_cast<const float4*>(pred2);
        for (int i = tid; i < (NN * 3) / 4; i += THREADS) {
            const float4 a = q2[i];
            const float4 b = q1[i];
            const float v[4] = {a.x - b.x, a.y - b.y, a.z - b.z, a.w - b.w};
            const int base = 4 * i;
            #pragma unroll
            for (int k = 0; k < 4; k++) {
                const int idx  = base + k;
                const int node = idx / 3;
                const int d    = idx - node * 3;
                (d == 0 ? sp0 : (d == 1 ? sp1 : sp2))[node] = v[k];
            }
        }
    }
    __syncthreads();

    // ---- main streaming loop: barrier-free, lane owns a row ----
    const long g   = (long)blockIdx.x * WARPS_PER_CTA + warp;
    const int  ub  = (int)((g * NUNITS) / NWARPS);
    const int  ue  = (int)(((g + 1) * NUNITS) / NWARPS);

    uint64_t acc[3][2];
    #pragma unroll
    for (int d = 0; d < 3; d++) { acc[d][0] = 0ull; acc[d][1] = 0ull; }

    int cur_rb = (ub < ue) ? (ub >> 6) : -1;

    for (int u = ub; u < ue; u++) {
        const int rb = u >> 6;        // rowblock (NCOLB = 64)
        const int cb = u & (NCOLB - 1);

        if (rb != cur_rb) {
            // flush dot accumulators for the finished rowblock
            const int row = cur_rb * ROWB + lane;
            #pragma unroll
            for (int d = 0; d < 3; d++) {
                atomicAdd(&g_dot[row * 3 + d], hadd2(acc[d][0]) + hadd2(acc[d][1]));
                acc[d][0] = 0ull; acc[d][1] = 0ull;
            }
            cur_rb = rb;
        }

        const int row     = rb * ROWB + lane;
        const int colbase = cb * COLB;
        const float4* __restrict__ Arow =
            reinterpret_cast<const float4*>(A + (size_t)row * NN + colbase);

        #pragma unroll 8
        for (int c = 0; c < COLB / 4; c++) {
            const float4 av = Arow[c];
            const int col = colbase + c * 4;

            // exact integer column sums for this warp's 32 rows
            const unsigned b0 = __ballot_sync(0xFFFFFFFFu, av.x != 0.0f);
            const unsigned b1 = __ballot_sync(0xFFFFFFFFu, av.y != 0.0f);
            const unsigned b2 = __ballot_sync(0xFFFFFFFFu, av.z != 0.0f);
            const unsigned b3 = __ballot_sync(0xFFFFFFFFu, av.w != 0.0f);
            const unsigned bb = (lane == 0) ? b0 : (lane == 1) ? b1
                              : (lane == 2) ? b2 : b3;
            if (lane < 4) atomicAdd(&g_deg[col + lane], __popc(bb));

            // packed dot accumulation (3 dims)
            const uint64_t ax = pack2(av.x, av.y);
            const uint64_t ay = pack2(av.z, av.w);
            const ulonglong2 p0 = *reinterpret_cast<const ulonglong2*>(sp0 + col);
            const ulonglong2 p1 = *reinterpret_cast<const ulonglong2*>(sp1 + col);
            const ulonglong2 p2 = *reinterpret_cast<const ulonglong2*>(sp2 + col);
            acc[0][0] = ffma2(ax, p0.x, acc[0][0]);
            acc[0][1] = ffma2(ay, p0.y, acc[0][1]);
            acc[1][0] = ffma2(ax, p1.x, acc[1][0]);
            acc[1][1] = ffma2(ay, p1.y, acc[1][1]);
            acc[2][0] = ffma2(ax, p2.x, acc[2][0]);
            acc[2][1] = ffma2(ay, p2.y, acc[2][1]);
        }
    }

    // final flush
    if (cur_rb >= 0) {
        const int row = cur_rb * ROWB + lane;
        #pragma unroll
        for (int d = 0; d < 3; d++)
            atomicAdd(&g_dot[row * 3 + d], hadd2(acc[d][0]) + hadd2(acc[d][1]));
    }

    // ---- last CTA computes the loss, then re-zeros scratch ----
    __shared__ int isLast;
    __syncthreads();
    if (tid == 0) {
        __threadfence();
        isLast = (atomicAdd(&g_done, 1) == NCTA - 1);
    }
    __syncthreads();

    if (isLast) {
        __threadfence();
        float s = 0.0f;
        for (int i = tid; i < NN; i += THREADS) {
            const float inv = 1.0f / (float)g_deg[i];
            const float d0 = sp0[i] - g_dot[3 * i + 0] * inv;
            const float d1 = sp1[i] - g_dot[3 * i + 1] * inv;
            const float d2 = sp2[i] - g_dot[3 * i + 2] * inv;
            s += d0 * d0 + d1 * d1 + d2 * d2;
        }
        s += __shfl_down_sync(0xFFFFFFFFu, s, 16);
        s += __shfl_down_sync(0xFFFFFFFFu, s, 8);
        s += __shfl_down_sync(0xFFFFFFFFu, s, 4);
        s += __shfl_down_sync(0xFFFFFFFFu, s, 2);
        s += __shfl_down_sync(0xFFFFFFFFu, s, 1);
        if (lane == 0) red[warp] = s;
        __syncthreads();
        if (tid == 0) {
            float v = 0.0f;
            #pragma unroll
            for (int w = 0; w < WARPS_PER_CTA; w++) v += red[w];
            out[0] = v;
        }
        // re-zero scratch for the next (graph-replayed) launch
        for (int i = tid; i < NN; i += THREADS) g_deg[i] = 0;
        for (int i = tid; i < NN * 3; i += THREADS) g_dot[i] = 0.0f;
        __syncthreads();
        if (tid == 0) g_done = 0;
    }
}

extern "C" void kernel_launch(void* const* d_in, const int* in_sizes, int n_in,
                              void* d_out, int out_size) {
    const float* pred1 = (const float*)d_in[0];
    const float* pred2 = (const float*)d_in[1];
    const float* A     = (const float*)d_in[2];
    float* out = (float*)d_out;

    const int smem_bytes = (3 * NN + 16) * (int)sizeof(float);
    cudaFuncSetAttribute(lap_kernel,
                         cudaFuncAttributeMaxDynamicSharedMemorySize, smem_bytes);
    lap_kernel<<<NCTA, THREADS, smem_bytes>>>(pred1, pred2, A, out);
}

// round 5
// speedup vs baseline: 1.7830x; 1.7830x over previous
#include <cuda_runtime.h>
#include <cstdint>

#define NN      8192
#define THREADS 512
#define NCTA    148
#define WPC     (THREADS / 32)        // 16 warps per CTA
#define NWARPS  (NCTA * WPC)          // 2368 = 64 * 37
#define NSEG    64                    // column segments of 128 cols
#define SEGC    128
#define NRG     (NWARPS / NSEG)       // 37 rowgroups
#define RU      8                     // rows per inner iteration

// scratch: __device__ globals (allocation-free rule). Every slot has exactly
// one unconditional writer per launch -> graph-replay deterministic.
__device__ float g_degpart[NWARPS * SEGC];      // 1.2 MB
__device__ float g_dotpart[NSEG * NN * 3];      // 6.3 MB
__device__ float g_losspart[64];

__device__ __forceinline__ float warp_sum(float v) {
    v += __shfl_down_sync(0xFFFFFFFFu, v, 16);
    v += __shfl_down_sync(0xFFFFFFFFu, v, 8);
    v += __shfl_down_sync(0xFFFFFFFFu, v, 4);
    v += __shfl_down_sync(0xFFFFFFFFu, v, 2);
    v += __shfl_down_sync(0xFFFFFFFFu, v, 1);
    return v;
}

// ---------- kernel A: one streaming pass over A, warp-private ----------
__global__ void __launch_bounds__(THREADS, 1)
spmm_kernel(const float* __restrict__ pred1,
            const float* __restrict__ pred2,
            const float* __restrict__ A) {
    const int tid  = threadIdx.x;
    const int lane = tid & 31;
    const int warp = tid >> 5;

    const int w   = blockIdx.x * WPC + warp;
    const int seg = w & (NSEG - 1);
    const int rg  = w >> 6;
    const int col = seg * SEGC + lane * 4;     // this lane's 4 columns
    const int r0  = (rg * NN) / NRG;
    const int r1  = ((rg + 1) * NN) / NRG;

    // hoist p = pred2 - pred1 for this lane's 4 columns: p[j][d], 12 regs
    float p00, p01, p02, p10, p11, p12, p20, p21, p22, p30, p31, p32;
    {
        const float4* q1 = reinterpret_cast<const float4*>(pred1 + (size_t)col * 3);
        const float4* q2 = reinterpret_cast<const float4*>(pred2 + (size_t)col * 3);
        const float4 a0 = q2[0], b0 = q1[0];
        const float4 a1 = q2[1], b1 = q1[1];
        const float4 a2 = q2[2], b2 = q1[2];
        p00 = a0.x - b0.x; p01 = a0.y - b0.y; p02 = a0.z - b0.z;
        p10 = a0.w - b0.w; p11 = a1.x - b1.x; p12 = a1.y - b1.y;
        p20 = a1.z - b1.z; p21 = a1.w - b1.w; p22 = a2.x - b2.x;
        p30 = a2.y - b2.y; p31 = a2.z - b2.z; p32 = a2.w - b2.w;
    }

    float dg0 = 0.0f, dg1 = 0.0f, dg2 = 0.0f, dg3 = 0.0f;

    const float4* __restrict__ Abase =
        reinterpret_cast<const float4*>(A + (size_t)r0 * NN + col);
    const int rows = r1 - r0;
    const int stride4 = NN / 4;                // float4 stride between rows

    int r = 0;
    for (; r + RU <= rows; r += RU) {
        // front-batch RU independent row loads
        float4 av[RU];
        #pragma unroll
        for (int k = 0; k < RU; k++)
            av[k] = __ldcs(Abase + (size_t)(r + k) * stride4);

        float a0[RU], a1[RU], a2[RU];
        #pragma unroll
        for (int k = 0; k < RU; k++) {
            a0[k] = av[k].x * p00 + av[k].y * p10 + av[k].z * p20 + av[k].w * p30;
            a1[k] = av[k].x * p01 + av[k].y * p11 + av[k].z * p21 + av[k].w * p31;
            a2[k] = av[k].x * p02 + av[k].y * p12 + av[k].z * p22 + av[k].w * p32;
            dg0 += av[k].x; dg1 += av[k].y; dg2 += av[k].z; dg3 += av[k].w;
        }

        #pragma unroll
        for (int k = 0; k < RU; k++) {
            const float d0 = warp_sum(a0[k]);
            const float d1 = warp_sum(a1[k]);
            const float d2 = warp_sum(a2[k]);
            if (lane == 0) {
                float* dst = g_dotpart + ((size_t)seg * NN + (r0 + r + k)) * 3;
                dst[0] = d0; dst[1] = d1; dst[2] = d2;
            }
        }
    }
    for (; r < rows; r++) {                    // tail rows (<= RU-1)
        const float4 av = __ldcs(Abase + (size_t)r * stride4);
        const float d0 = warp_sum(av.x * p00 + av.y * p10 + av.z * p20 + av.w * p30);
        const float d1 = warp_sum(av.x * p01 + av.y * p11 + av.z * p21 + av.w * p31);
        const float d2 = warp_sum(av.x * p02 + av.y * p12 + av.z * p22 + av.w * p32);
        dg0 += av.x; dg1 += av.y; dg2 += av.z; dg3 += av.w;
        if (lane == 0) {
            float* dst = g_dotpart + ((size_t)seg * NN + (r0 + r)) * 3;
            dst[0] = d0; dst[1] = d1; dst[2] = d2;
        }
    }

    // flush deg partials for this warp's 128 columns (one float4 per lane)
    float4 dv; dv.x = dg0; dv.y = dg1; dv.z = dg2; dv.w = dg3;
    *reinterpret_cast<float4*>(g_degpart + (size_t)w * SEGC + lane * 4) = dv;
}

// ---------- kernel B: reduce partials, per-CTA loss partial ----------
__global__ void __launch_bounds__(128)
reduce_kernel(const float* __restrict__ pred1,
              const float* __restrict__ pred2) {
    __shared__ float red[4];
    const int tid  = threadIdx.x;
    const int lane = tid & 31;
    const int warp = tid >> 5;
    const int i    = blockIdx.x * 128 + tid;       // node id, grid 64 x 128

    // deg(i): sum over 37 rowgroup partials of this column
    const int seg = i >> 7;
    const int c   = i & (SEGC - 1);
    float deg = 0.0f;
    #pragma unroll
    for (int rg = 0; rg < NRG; rg++)
        deg += g_degpart[((size_t)rg * NSEG + seg) * SEGC + c];

    // dot(i): sum over 64 segment partials
    float t0 = 0.0f, t1 = 0.0f, t2 = 0.0f;
    #pragma unroll 8
    for (int s = 0; s < NSEG; s++) {
        const float* q = g_dotpart + ((size_t)s * NN + i) * 3;
        t0 += q[0]; t1 += q[1]; t2 += q[2];
    }

    const float inv = 1.0f / deg;
    const float p0 = pred2[3 * i + 0] - pred1[3 * i + 0];
    const float p1 = pred2[3 * i + 1] - pred1[3 * i + 1];
    const float p2 = pred2[3 * i + 2] - pred1[3 * i + 2];
    const float e0 = p0 - t0 * inv;
    const float e1 = p1 - t1 * inv;
    const float e2 = p2 - t2 * inv;
    float s = e0 * e0 + e1 * e1 + e2 * e2;

    s = warp_sum(s);
    if (lane == 0) red[warp] = s;
    __syncthreads();
    if (tid == 0)
        g_losspart[blockIdx.x] = red[0] + red[1] + red[2] + red[3];
}

// ---------- kernel C: final scalar ----------
__global__ void final_kernel(float* __restrict__ out) {
    const int t = threadIdx.x;                     // 32 threads
    float v = g_losspart[t] + g_losspart[t + 32];
    v = warp_sum(v);
    if (t == 0) out[0] = v;
}

extern "C" void kernel_launch(void* const* d_in, const int* in_sizes, int n_in,
                              void* d_out, int out_size) {
    const float* pred1 = (const float*)d_in[0];
    const float* pred2 = (const float*)d_in[1];
    const float* A     = (const float*)d_in[2];
    float* out = (float*)d_out;

    spmm_kernel<<<NCTA, THREADS>>>(pred1, pred2, A);
    reduce_kernel<<<64, 128>>>(pred1, pred2);
    final_kernel<<<1, 32>>>(out);
}

// round 6
// speedup vs baseline: 2.3881x; 1.3394x over previous
#include <cuda_runtime.h>
#include <cstdint>

#define NN      8192
#define THREADS 512
#define NCTA    148
#define WPC     (THREADS / 32)        // 16 warps per CTA
#define NWARPS  (NCTA * WPC)          // 2368 = 32 * 74
#define NSEG    32                    // column segments of 256 cols
#define SEGC    256
#define NRG     (NWARPS / NSEG)       // 74 rowgroups (~110 rows each)
#define RU      4                     // rows per inner iteration

// scratch: __device__ globals (allocation-free rule). Every slot has exactly
// one unconditional writer per launch -> graph-replay deterministic.
__device__ float g_degpart[NWARPS * SEGC];      // 2.4 MB
__device__ float g_dotpart[NSEG * NN * 3];      // 3.1 MB
__device__ float g_losspart[64];

__device__ __forceinline__ float warp_sum(float v) {
    v += __shfl_down_sync(0xFFFFFFFFu, v, 16);
    v += __shfl_down_sync(0xFFFFFFFFu, v, 8);
    v += __shfl_down_sync(0xFFFFFFFFu, v, 4);
    v += __shfl_down_sync(0xFFFFFFFFu, v, 2);
    v += __shfl_down_sync(0xFFFFFFFFu, v, 1);
    return v;
}

// one butterfly step: live values v[0..L-1] -> v[0..L/2-1], width W
template <int L, int W>
__device__ __forceinline__ void bstep(float* v, int lane) {
    const int hi = lane & W;
    #pragma unroll
    for (int j = 0; j < L / 2; j++) {
        const float sent = hi ? v[j] : v[j + L / 2];
        const float got  = __shfl_xor_sync(0xFFFFFFFFu, sent, W);
        v[j] = (hi ? v[j + L / 2] : v[j]) + got;
    }
}

// ---------- kernel A: one streaming pass over A ----------
__global__ void __launch_bounds__(THREADS, 1)
spmm_kernel(const float* __restrict__ pred1,
            const float* __restrict__ pred2,
            const float* __restrict__ A) {
    const int tid  = threadIdx.x;
    const int lane = tid & 31;
    const int warp = tid >> 5;

    const int w    = blockIdx.x * WPC + warp;
    const int seg  = w & (NSEG - 1);
    const int rg   = w >> 5;
    const int col0 = seg * SEGC + lane * 8;        // this lane's 8 columns
    const int r0   = (rg * NN) / NRG;
    const int r1   = ((rg + 1) * NN) / NRG;

    // hoist p = pred2 - pred1 for this lane's 8 columns: p[jc][d], 24 regs
    float p[8][3];
    {
        const float4* q1 = reinterpret_cast<const float4*>(pred1 + (size_t)col0 * 3);
        const float4* q2 = reinterpret_cast<const float4*>(pred2 + (size_t)col0 * 3);
        float tmp[24];
        #pragma unroll
        for (int k = 0; k < 6; k++) {
            const float4 a = q2[k];
            const float4 b = q1[k];
            tmp[4 * k + 0] = a.x - b.x;
            tmp[4 * k + 1] = a.y - b.y;
            tmp[4 * k + 2] = a.z - b.z;
            tmp[4 * k + 3] = a.w - b.w;
        }
        #pragma unroll
        for (int j = 0; j < 24; j++) p[j / 3][j % 3] = tmp[j];
    }

    float dg[8];
    #pragma unroll
    for (int j = 0; j < 8; j++) dg[j] = 0.0f;

    const float4* __restrict__ Abase =
        reinterpret_cast<const float4*>(A + (size_t)r0 * NN + col0);
    const int stride4 = NN / 4;
    const int rows = r1 - r0;

    int r = 0;
    for (; r + RU <= rows; r += RU) {
        // front-batch 2*RU = 8 independent loads
        float4 av[RU][2];
        #pragma unroll
        for (int k = 0; k < RU; k++) {
            const float4* rp = Abase + (size_t)(r + k) * stride4;
            av[k][0] = __ldcs(rp);
            av[k][1] = __ldcs(rp + 1);
        }

        float v[16];
        #pragma unroll
        for (int k = 0; k < RU; k++) {
            const float4 a0 = av[k][0], a1 = av[k][1];
            #pragma unroll
            for (int d = 0; d < 3; d++) {
                v[k * 3 + d] =
                    a0.x * p[0][d] + a0.y * p[1][d] + a0.z * p[2][d] + a0.w * p[3][d] +
                    a1.x * p[4][d] + a1.y * p[5][d] + a1.z * p[6][d] + a1.w * p[7][d];
            }
            dg[0] += a0.x; dg[1] += a0.y; dg[2] += a0.z; dg[3] += a0.w;
            dg[4] += a1.x; dg[5] += a1.y; dg[6] += a1.z; dg[7] += a1.w;
        }
        #pragma unroll
        for (int j = 12; j < 16; j++) v[j] = 0.0f;

        // multi-value butterfly: after 5 steps, lane pair floor(l/2)
        // holds the full 32-lane sum of value floor(l/2)
        bstep<16, 16>(v, lane);
        bstep<8, 8>(v, lane);
        bstep<4, 4>(v, lane);
        bstep<2, 2>(v, lane);
        v[0] += __shfl_xor_sync(0xFFFFFFFFu, v[0], 1);

        const int k = lane >> 1;                   // value index
        if ((lane & 1) == 0 && k < 12)
            g_dotpart[((size_t)seg * NN + (r0 + r)) * 3 + k] = v[0];
    }

    // tail rows (<= RU-1): plain warp reduction
    for (; r < rows; r++) {
        const float4* rp = Abase + (size_t)r * stride4;
        const float4 a0 = __ldcs(rp);
        const float4 a1 = __ldcs(rp + 1);
        float t[3];
        #pragma unroll
        for (int d = 0; d < 3; d++) {
            t[d] = warp_sum(
                a0.x * p[0][d] + a0.y * p[1][d] + a0.z * p[2][d] + a0.w * p[3][d] +
                a1.x * p[4][d] + a1.y * p[5][d] + a1.z * p[6][d] + a1.w * p[7][d]);
        }
        dg[0] += a0.x; dg[1] += a0.y; dg[2] += a0.z; dg[3] += a0.w;
        dg[4] += a1.x; dg[5] += a1.y; dg[6] += a1.z; dg[7] += a1.w;
        if (lane == 0) {
            float* dst = g_dotpart + ((size_t)seg * NN + (r0 + r)) * 3;
            dst[0] = t[0]; dst[1] = t[1]; dst[2] = t[2];
        }
    }

    // flush deg partials for this warp's 256 columns (2 float4 per lane)
    {
        float* dst = g_degpart + (size_t)w * SEGC + lane * 8;
        float4 d0; d0.x = dg[0]; d0.y = dg[1]; d0.z = dg[2]; d0.w = dg[3];
        float4 d1; d1.x = dg[4]; d1.y = dg[5]; d1.z = dg[6]; d1.w = dg[7];
        *reinterpret_cast<float4*>(dst)     = d0;
        *reinterpret_cast<float4*>(dst + 4) = d1;
    }
}

// ---------- kernel B: reduce partials, per-CTA loss partial ----------
__global__ void __launch_bounds__(128)
reduce_kernel(const float* __restrict__ pred1,
              const float* __restrict__ pred2) {
    __shared__ float red[4];
    const int tid  = threadIdx.x;
    const int lane = tid & 31;
    const int warp = tid >> 5;
    const int i    = blockIdx.x * 128 + tid;       // node id, grid 64 x 128

    // deg(i): sum over 74 rowgroup partials of this column
    const int seg = i >> 8;
    const int c   = i & (SEGC - 1);
    float deg = 0.0f;
    #pragma unroll 2
    for (int rg = 0; rg < NRG; rg++)
        deg += g_degpart[((size_t)rg * NSEG + seg) * SEGC + c];

    // dot(i): sum over 32 segment partials
    float t0 = 0.0f, t1 = 0.0f, t2 = 0.0f;
    #pragma unroll 8
    for (int s = 0; s < NSEG; s++) {
        const float* q = g_dotpart + ((size_t)s * NN + i) * 3;
        t0 += q[0]; t1 += q[1]; t2 += q[2];
    }

    const float inv = 1.0f / deg;
    const float p0 = pred2[3 * i + 0] - pred1[3 * i + 0];
    const float p1 = pred2[3 * i + 1] - pred1[3 * i + 1];
    const float p2 = pred2[3 * i + 2] - pred1[3 * i + 2];
    const float e0 = p0 - t0 * inv;
    const float e1 = p1 - t1 * inv;
    const float e2 = p2 - t2 * inv;
    float s = e0 * e0 + e1 * e1 + e2 * e2;

    s = warp_sum(s);
    if (lane == 0) red[warp] = s;
    __syncthreads();
    if (tid == 0)
        g_losspart[blockIdx.x] = red[0] + red[1] + red[2] + red[3];
}

// ---------- kernel C: final scalar ----------
__global__ void final_kernel(float* __restrict__ out) {
    const int t = threadIdx.x;                     // 32 threads
    float v = g_losspart[t] + g_losspart[t + 32];
    v = warp_sum(v);
    if (t == 0) out[0] = v;
}

extern "C" void kernel_launch(void* const* d_in, const int* in_sizes, int n_in,
                              void* d_out, int out_size) {
    const float* pred1 = (const float*)d_in[0];
    const float* pred2 = (const float*)d_in[1];
    const float* A     = (const float*)d_in[2];
    float* out = (float*)d_out;

    spmm_kernel<<<NCTA, THREADS>>>(pred1, pred2, A);
    reduce_kernel<<<64, 128>>>(pred1, pred2);
    final_kernel<<<1, 32>>>(out);
}

// round 7
// speedup vs baseline: 2.7393x; 1.1471x over previous
#include <cuda_runtime.h>
#include <cstdint>

#define NN      8192
#define THREADS 512
#define NCTA    148
#define WPC     (THREADS / 32)        // 16 warps per CTA
#define NWARPS  (NCTA * WPC)          // 2368 = 32 * 74
#define NSEG    32                    // column segments of 256 cols
#define SEGC    256
#define NRG     (NWARPS / NSEG)       // 74 rowgroups (~110 rows each)
#define RU      5                     // rows per inner iteration (15 values + pad)
#define RBLKS   128                   // reduce grid

// scratch: __device__ globals (allocation-free rule). Every slot has exactly
// one unconditional writer per launch -> graph-replay deterministic.
__device__ float g_degpart[NWARPS * SEGC];      // 2.4 MB
__device__ float g_dotpart[NSEG * NN * 3];      // 3.1 MB
__device__ float g_losspart[RBLKS];

__device__ __forceinline__ float warp_sum(float v) {
    v += __shfl_down_sync(0xFFFFFFFFu, v, 16);
    v += __shfl_down_sync(0xFFFFFFFFu, v, 8);
    v += __shfl_down_sync(0xFFFFFFFFu, v, 4);
    v += __shfl_down_sync(0xFFFFFFFFu, v, 2);
    v += __shfl_down_sync(0xFFFFFFFFu, v, 1);
    return v;
}

// one butterfly step: live values v[0..L-1] -> v[0..L/2-1], width W
template <int L, int W>
__device__ __forceinline__ void bstep(float* v, int lane) {
    const int hi = lane & W;
    #pragma unroll
    for (int j = 0; j < L / 2; j++) {
        const float sent = hi ? v[j] : v[j + L / 2];
        const float got  = __shfl_xor_sync(0xFFFFFFFFu, sent, W);
        v[j] = (hi ? v[j + L / 2] : v[j]) + got;
    }
}

// ---------- kernel A: one streaming pass over A ----------
__global__ void __launch_bounds__(THREADS, 1)
spmm_kernel(const float* __restrict__ pred1,
            const float* __restrict__ pred2,
            const float* __restrict__ A) {
    const int tid  = threadIdx.x;
    const int lane = tid & 31;
    const int warp = tid >> 5;

    const int w    = blockIdx.x * WPC + warp;
    const int seg  = w & (NSEG - 1);
    const int rg   = w >> 5;
    const int col0 = seg * SEGC + lane * 8;        // this lane's 8 columns
    const int r0   = (rg * NN) / NRG;
    const int r1   = ((rg + 1) * NN) / NRG;

    // hoist p = pred2 - pred1 for this lane's 8 columns: p[jc][d], 24 regs
    float p[8][3];
    {
        const float4* q1 = reinterpret_cast<const float4*>(pred1 + (size_t)col0 * 3);
        const float4* q2 = reinterpret_cast<const float4*>(pred2 + (size_t)col0 * 3);
        float tmp[24];
        #pragma unroll
        for (int k = 0; k < 6; k++) {
            const float4 a = q2[k];
            const float4 b = q1[k];
            tmp[4 * k + 0] = a.x - b.x;
            tmp[4 * k + 1] = a.y - b.y;
            tmp[4 * k + 2] = a.z - b.z;
            tmp[4 * k + 3] = a.w - b.w;
        }
        #pragma unroll
        for (int j = 0; j < 24; j++) p[j / 3][j % 3] = tmp[j];
    }

    float dg[8];
    #pragma unroll
    for (int j = 0; j < 8; j++) dg[j] = 0.0f;

    const float4* __restrict__ Abase =
        reinterpret_cast<const float4*>(A + (size_t)r0 * NN + col0);
    const int stride4 = NN / 4;
    const int rows = r1 - r0;

    int r = 0;
    for (; r + RU <= rows; r += RU) {
        // front-batch 2*RU = 10 independent loads
        float4 av[RU][2];
        #pragma unroll
        for (int k = 0; k < RU; k++) {
            const float4* rp = Abase + (size_t)(r + k) * stride4;
            av[k][0] = __ldcs(rp);
            av[k][1] = __ldcs(rp + 1);
        }

        float v[16];
        #pragma unroll
        for (int k = 0; k < RU; k++) {
            const float4 a0 = av[k][0], a1 = av[k][1];
            #pragma unroll
            for (int d = 0; d < 3; d++) {
                v[k * 3 + d] =
                    a0.x * p[0][d] + a0.y * p[1][d] + a0.z * p[2][d] + a0.w * p[3][d] +
                    a1.x * p[4][d] + a1.y * p[5][d] + a1.z * p[6][d] + a1.w * p[7][d];
            }
            dg[0] += a0.x; dg[1] += a0.y; dg[2] += a0.z; dg[3] += a0.w;
            dg[4] += a1.x; dg[5] += a1.y; dg[6] += a1.z; dg[7] += a1.w;
        }
        v[15] = 0.0f;                              // pad to 16

        // multi-value butterfly: after 5 steps, lane pair floor(l/2)
        // holds the full 32-lane sum of value floor(l/2)
        bstep<16, 16>(v, lane);
        bstep<8, 8>(v, lane);
        bstep<4, 4>(v, lane);
        bstep<2, 2>(v, lane);
        v[0] += __shfl_xor_sync(0xFFFFFFFFu, v[0], 1);

        const int k = lane >> 1;                   // value index 0..15
        if ((lane & 1) == 0 && k < 15)
            g_dotpart[((size_t)seg * NN + (r0 + r)) * 3 + k] = v[0];
    }

    // tail rows (<= RU-1): plain warp reduction
    for (; r < rows; r++) {
        const float4* rp = Abase + (size_t)r * stride4;
        const float4 a0 = __ldcs(rp);
        const float4 a1 = __ldcs(rp + 1);
        float t[3];
        #pragma unroll
        for (int d = 0; d < 3; d++) {
            t[d] = warp_sum(
                a0.x * p[0][d] + a0.y * p[1][d] + a0.z * p[2][d] + a0.w * p[3][d] +
                a1.x * p[4][d] + a1.y * p[5][d] + a1.z * p[6][d] + a1.w * p[7][d]);
        }
        dg[0] += a0.x; dg[1] += a0.y; dg[2] += a0.z; dg[3] += a0.w;
        dg[4] += a1.x; dg[5] += a1.y; dg[6] += a1.z; dg[7] += a1.w;
        if (lane == 0) {
            float* dst = g_dotpart + ((size_t)seg * NN + (r0 + r)) * 3;
            dst[0] = t[0]; dst[1] = t[1]; dst[2] = t[2];
        }
    }

    // flush deg partials for this warp's 256 columns (2 float4 per lane)
    {
        float* dst = g_degpart + (size_t)w * SEGC + lane * 8;
        float4 d0; d0.x = dg[0]; d0.y = dg[1]; d0.z = dg[2]; d0.w = dg[3];
        float4 d1; d1.x = dg[4]; d1.y = dg[5]; d1.z = dg[6]; d1.w = dg[7];
        *reinterpret_cast<float4*>(dst)     = d0;
        *reinterpret_cast<float4*>(dst + 4) = d1;
    }
}

// ---------- kernel B: reduce partials, 4 threads per node ----------
__global__ void __launch_bounds__(256)
reduce_kernel(const float* __restrict__ pred1,
              const float* __restrict__ pred2) {
    __shared__ float red[8];
    const int tid  = threadIdx.x;
    const int lane = tid & 31;
    const int warp = tid >> 5;
    const int g    = blockIdx.x * 256 + tid;       // 128*256 = 32768 = 8192*4
    const int i    = g >> 2;                       // node id
    const int j    = g & 3;                        // sub-thread

    // deg(i): sub j sums rowgroups j, j+4, ...
    const int seg = i >> 8;
    const int c   = i & (SEGC - 1);
    float deg = 0.0f;
    for (int rg = j; rg < NRG; rg += 4)
        deg += g_degpart[((size_t)rg * NSEG + seg) * SEGC + c];

    // dot(i): sub j sums segments j, j+4, ... (8 each)
    float t0 = 0.0f, t1 = 0.0f, t2 = 0.0f;
    #pragma unroll
    for (int s = j; s < NSEG; s += 4) {
        const float* q = g_dotpart + ((size_t)s * NN + i) * 3;
        t0 += q[0]; t1 += q[1]; t2 += q[2];
    }

    // combine the 4 sub-threads (lanes 4k..4k+3 hold node k's partials)
    deg += __shfl_xor_sync(0xFFFFFFFFu, deg, 1);
    deg += __shfl_xor_sync(0xFFFFFFFFu, deg, 2);
    t0  += __shfl_xor_sync(0xFFFFFFFFu, t0, 1);
    t0  += __shfl_xor_sync(0xFFFFFFFFu, t0, 2);
    t1  += __shfl_xor_sync(0xFFFFFFFFu, t1, 1);
    t1  += __shfl_xor_sync(0xFFFFFFFFu, t1, 2);
    t2  += __shfl_xor_sync(0xFFFFFFFFu, t2, 1);
    t2  += __shfl_xor_sync(0xFFFFFFFFu, t2, 2);

    float s = 0.0f;
    if (j == 0) {
        const float inv = 1.0f / deg;
        const float p0 = pred2[3 * i + 0] - pred1[3 * i + 0];
        const float p1 = pred2[3 * i + 1] - pred1[3 * i + 1];
        const float p2 = pred2[3 * i + 2] - pred1[3 * i + 2];
        const float e0 = p0 - t0 * inv;
        const float e1 = p1 - t1 * inv;
        const float e2 = p2 - t2 * inv;
        s = e0 * e0 + e1 * e1 + e2 * e2;
    }

    s = warp_sum(s);
    if (lane == 0) red[warp] = s;
    __syncthreads();
    if (tid == 0) {
        float v = 0.0f;
        #pragma unroll
        for (int k = 0; k < 8; k++) v += red[k];
        g_losspart[blockIdx.x] = v;
    }
}

// ---------- kernel C: final scalar ----------
__global__ void final_kernel(float* __restrict__ out) {
    __shared__ float red[4];
    const int tid  = threadIdx.x;                  // 128 threads
    const int lane = tid & 31;
    const int warp = tid >> 5;
    float v = warp_sum(g_losspart[tid]);
    if (lane == 0) red[warp] = v;
    __syncthreads();
    if (tid == 0) out[0] = red[0] + red[1] + red[2] + red[3];
}

extern "C" void kernel_launch(void* const* d_in, const int* in_sizes, int n_in,
                              void* d_out, int out_size) {
    const float* pred1 = (const float*)d_in[0];
    const float* pred2 = (const float*)d_in[1];
    const float* A     = (const float*)d_in[2];
    float* out = (float*)d_out;

    spmm_kernel<<<NCTA, THREADS>>>(pred1, pred2, A);
    reduce_kernel<<<RBLKS, 256>>>(pred1, pred2);
    final_kernel<<<1, RBLKS>>>(out);
}